// round 17
// baseline (speedup 1.0000x reference)
#include <cuda_runtime.h>
#include <cuda_bf16.h>
#include <cstdint>

// DiffPool: B=8, N=2048, F=C=K=128.
// out: X_pooled[8,128,128] | A_pooled[8,128,128] | S[8,2048,128] | LP_loss | entr_loss
//
// A exactly binary -> exact bf16; HMMA mma.sync m16n8k16 fp32-acc.
//   K2T (3-term hi/lo): [Xe | Yp] = X @ [We | Wp]
//   P1: logits = d*(A@Yp + Yp) -> fused softmax -> S fp32, Shi/Slo, dShi, entropy
//   P2: A@[Shi | dShi] (64x256 tile) -> Thi/Tlo, U=d*acc+d^2*S -> Uhi/Ulo
//   K5T (hi/lo, hh+hl+lh): X_pooled = U^T Xe, A_pooled = S^T T, G = S^T S
//   LP^2_b = sumA_b - 2 tr(A_pooled_b) + ||G_b||_F^2
// This round: k1/k0 stores vectorized to STG.128 (k1 was ~45us: 201MB HBM
// stream throttled by 16.7M 4-byte stores); p1 reverted to proven R14 config.

#define BB 8
#define NN 2048
#define ROWS (BB*NN)
#define OUT_AP 131072
#define OUT_S  262144
#define OUT_LP 2359296
#define OUT_ENT 2359297

#define P1BUF 25600
#define P1SMEM (2*P1BUF)
#define P2BUF 41984
#define P2SMEM (2*P2BUF)
#define K5BUF 32768
#define K5SMEM (3*K5BUF)
#define K2BUF 43008
#define K2SMEM (2*K2BUF)

// ---- scratch ----
__device__ __nv_bfloat16 g_Abf[(size_t)ROWS*2048];
__device__ __nv_bfloat16 g_Xh[(size_t)ROWS*128];
__device__ __nv_bfloat16 g_Xl[(size_t)ROWS*128];
__device__ __nv_bfloat16 g_Wh[128*256];
__device__ __nv_bfloat16 g_Wl[128*256];
__device__ float g_Yp[(size_t)ROWS*128];
__device__ __nv_bfloat16 g_Yphi[(size_t)ROWS*128];
__device__ __nv_bfloat16 g_Xehi[(size_t)ROWS*128];
__device__ __nv_bfloat16 g_Xelo[(size_t)ROWS*128];
__device__ __nv_bfloat16 g_Shi[(size_t)ROWS*128];
__device__ __nv_bfloat16 g_Slo[(size_t)ROWS*128];
__device__ __nv_bfloat16 g_dShi[(size_t)ROWS*128];
__device__ __nv_bfloat16 g_Thi[(size_t)ROWS*128];
__device__ __nv_bfloat16 g_Tlo[(size_t)ROWS*128];
__device__ __nv_bfloat16 g_Uhi[(size_t)ROWS*128];
__device__ __nv_bfloat16 g_Ulo[(size_t)ROWS*128];
__device__ float g_d[ROWS];
__device__ int   g_nnz[ROWS];
__device__ float g_entrRow[ROWS];
__device__ float g_part[(size_t)3*8*8*16384];
__device__ float g_G[8*128*128];

// ---------------- PTX helpers ----------------
__device__ __forceinline__ uint32_t smem_u32(const void* p) {
    uint32_t a;
    asm("{ .reg .u64 t; cvta.to.shared.u64 t, %1; cvt.u32.u64 %0, t; }" : "=r"(a) : "l"(p));
    return a;
}
__device__ __forceinline__ void cpa16(uint32_t s, const void* g) {
    asm volatile("cp.async.cg.shared.global [%0], [%1], 16;" :: "r"(s), "l"(g));
}
#define CPA_COMMIT() asm volatile("cp.async.commit_group;" ::: "memory")
#define CPA_WAIT1()  asm volatile("cp.async.wait_group 1;" ::: "memory")
#define CPA_WAIT0()  asm volatile("cp.async.wait_group 0;" ::: "memory")

__device__ __forceinline__ void ldsm4(uint32_t& r0, uint32_t& r1, uint32_t& r2, uint32_t& r3,
                                      uint32_t a) {
    asm volatile("ldmatrix.sync.aligned.m8n8.x4.shared.b16 {%0,%1,%2,%3}, [%4];"
                 : "=r"(r0), "=r"(r1), "=r"(r2), "=r"(r3) : "r"(a));
}
__device__ __forceinline__ void ldsm4t(uint32_t& r0, uint32_t& r1, uint32_t& r2, uint32_t& r3,
                                       uint32_t a) {
    asm volatile("ldmatrix.sync.aligned.m8n8.x4.trans.shared.b16 {%0,%1,%2,%3}, [%4];"
                 : "=r"(r0), "=r"(r1), "=r"(r2), "=r"(r3) : "r"(a));
}
__device__ __forceinline__ void mma_bf16(float4& d, const uint32_t* a, const uint32_t* b) {
    asm volatile("mma.sync.aligned.m16n8k16.row.col.f32.bf16.bf16.f32 "
                 "{%0,%1,%2,%3}, {%4,%5,%6,%7}, {%8,%9}, {%0,%1,%2,%3};"
                 : "+f"(d.x), "+f"(d.y), "+f"(d.z), "+f"(d.w)
                 : "r"(a[0]), "r"(a[1]), "r"(a[2]), "r"(a[3]), "r"(b[0]), "r"(b[1]));
}
__device__ __forceinline__ void store_hilo2(__nv_bfloat16* Hd, __nv_bfloat16* Ld,
                                            size_t base, float vx, float vy) {
    __nv_bfloat16 h0 = __float2bfloat16_rn(vx);
    __nv_bfloat16 h1 = __float2bfloat16_rn(vy);
    __nv_bfloat16 l0 = __float2bfloat16_rn(vx - __bfloat162float(h0));
    __nv_bfloat16 l1 = __float2bfloat16_rn(vy - __bfloat162float(h1));
    *reinterpret_cast<__nv_bfloat162*>(Hd + base) = __halves2bfloat162(h0, h1);
    *reinterpret_cast<__nv_bfloat162*>(Ld + base) = __halves2bfloat162(l0, l1);
}
__device__ __forceinline__ uint32_t pack2(float a, float b) {
    __nv_bfloat162 p = __floats2bfloat162_rn(a, b);
    return *reinterpret_cast<uint32_t*>(&p);
}

// =====================================================================
// K1: row-sum of A + exact bf16 conversion (one STG.128 per thread)
// =====================================================================
__global__ void k1_scan(const float* __restrict__ A) {
    int row = blockIdx.x;
    int t = threadIdx.x;                     // 256: thread t -> cols [8t, 8t+8)
    const float4* ar = reinterpret_cast<const float4*>(A + (size_t)row * NN);
    float4 v0 = ar[t * 2];
    float4 v1 = ar[t * 2 + 1];
    int cnt = (v0.x != 0.f) + (v0.y != 0.f) + (v0.z != 0.f) + (v0.w != 0.f)
            + (v1.x != 0.f) + (v1.y != 0.f) + (v1.z != 0.f) + (v1.w != 0.f);
    uint4 pk;
    pk.x = pack2(v0.x, v0.y);
    pk.y = pack2(v0.z, v0.w);
    pk.z = pack2(v1.x, v1.y);
    pk.w = pack2(v1.z, v1.w);
    *reinterpret_cast<uint4*>(g_Abf + (size_t)row * NN + t * 8) = pk;

    int lane = t & 31, w = t >> 5;
    #pragma unroll
    for (int o = 16; o > 0; o >>= 1) cnt += __shfl_xor_sync(0xffffffffu, cnt, o);
    __shared__ int wtot[8];
    if (lane == 0) wtot[w] = cnt;
    __syncthreads();
    if (t == 0) {
        int s = 0;
        #pragma unroll
        for (int i = 0; i < 8; i++) s += wtot[i];
        g_nnz[row] = s;
        g_d[row] = rsqrtf((float)s + 1.0f);
    }
}

// =====================================================================
// K0: X -> hi/lo bf16 (8 floats/thread, STG.128 per array)
// =====================================================================
__global__ void k0_convX(const float* __restrict__ X) {
    size_t idx = (size_t)blockIdx.x * 256 + threadIdx.x;   // 0..262143
    const float4* xp = reinterpret_cast<const float4*>(X);
    float4 v0 = xp[idx * 2];
    float4 v1 = xp[idx * 2 + 1];
    float vs[8] = {v0.x, v0.y, v0.z, v0.w, v1.x, v1.y, v1.z, v1.w};
    uint32_t hw[4], lw[4];
    #pragma unroll
    for (int q = 0; q < 4; q++) {
        __nv_bfloat16 h0 = __float2bfloat16_rn(vs[q * 2]);
        __nv_bfloat16 h1 = __float2bfloat16_rn(vs[q * 2 + 1]);
        float l0 = vs[q * 2] - __bfloat162float(h0);
        float l1 = vs[q * 2 + 1] - __bfloat162float(h1);
        __nv_bfloat162 hp = __halves2bfloat162(h0, h1);
        __nv_bfloat162 lp = __floats2bfloat162_rn(l0, l1);
        hw[q] = *reinterpret_cast<uint32_t*>(&hp);
        lw[q] = *reinterpret_cast<uint32_t*>(&lp);
    }
    *reinterpret_cast<uint4*>(g_Xh + idx * 8) = make_uint4(hw[0], hw[1], hw[2], hw[3]);
    *reinterpret_cast<uint4*>(g_Xl + idx * 8) = make_uint4(lw[0], lw[1], lw[2], lw[3]);
}

// =====================================================================
// KW: [We | Wp] -> hi/lo bf16, layout [128][256]
// =====================================================================
__global__ void kW_conv(const float* __restrict__ We, const float* __restrict__ Wp) {
    int idx = blockIdx.x * 256 + threadIdx.x;
    int k = idx >> 6, c4 = idx & 63;
    int c = c4 * 4;
    const float* src = (c < 128) ? (We + k * 128 + c) : (Wp + k * 128 + (c - 128));
    float4 v = *reinterpret_cast<const float4*>(src);
    size_t base = (size_t)k * 256 + c;
    store_hilo2(g_Wh, g_Wl, base,     v.x, v.y);
    store_hilo2(g_Wh, g_Wl, base + 2, v.z, v.w);
}

// =====================================================================
// K2T: [Xe | Yp] = X @ [We | Wp] via 3-term hi/lo HMMA.
// =====================================================================
__global__ void __launch_bounds__(256, 2)
k2t_xw() {
    extern __shared__ char smem[];
    uint32_t sb = smem_u32(smem);
    int tid = threadIdx.x;
    int wid = tid >> 5, lane = tid & 31;
    int n0 = blockIdx.x * 64;
    const __nv_bfloat16* Xhg = g_Xh + (size_t)n0 * 128;
    const __nv_bfloat16* Xlg = g_Xl + (size_t)n0 * 128;

    float4 acc[2][8];
    #pragma unroll
    for (int i = 0; i < 2; i++)
        #pragma unroll
        for (int j = 0; j < 8; j++) acc[i][j] = make_float4(0.f, 0.f, 0.f, 0.f);

    int n0w = (wid >> 2) * 32;
    int cw = wid & 3;
    int c0l = (cw & 1) * 64;
    uint32_t bh_off = (cw >= 2) ? 26624u : 10240u;
    int sel = lane >> 3, rr = lane & 7;

    auto stage = [&](int ch, int buf) {
        uint32_t s0 = sb + buf * K2BUF;
        int kc = ch * 32;
        #pragma unroll
        for (int q = 0; q < 2; q++) {
            int idx = tid + q * 256;
            int which = idx >> 8, r = idx & 255;
            int row = r >> 2, u = r & 3;
            const __nv_bfloat16* src = which ? Xlg : Xhg;
            cpa16(s0 + which * 5120 + row * 80 + u * 16,
                  src + (size_t)row * 128 + kc + u * 8);
        }
        #pragma unroll
        for (int q = 0; q < 8; q++) {
            int idx = tid + q * 256;
            int arr = idx >> 9, r = idx & 511;
            int k = r >> 4, u = r & 15;
            uint32_t so = k * 256 + ((u * 16) ^ ((k & 7) << 4));
            const __nv_bfloat16* src = (arr & 1) ? g_Wl : g_Wh;
            int cb = (arr >= 2) ? 128 : 0;
            cpa16(s0 + 10240 + arr * 8192 + so,
                  src + (size_t)(kc + k) * 256 + cb + u * 8);
        }
        CPA_COMMIT();
    };

    stage(0, 0);
    for (int ch = 0; ch < 4; ch++) {
        if (ch < 3) { stage(ch + 1, (ch + 1) & 1); CPA_WAIT1(); }
        else CPA_WAIT0();
        __syncthreads();
        uint32_t s0 = sb + (ch & 1) * K2BUF;
        #pragma unroll
        for (int ks = 0; ks < 2; ks++) {
            uint32_t xh[2][4], xl[2][4];
            #pragma unroll
            for (int i = 0; i < 2; i++) {
                int row = n0w + i * 16 + (sel & 1) * 8 + rr;
                uint32_t ad = row * 80 + ks * 32 + (sel >> 1) * 16;
                ldsm4(xh[i][0], xh[i][1], xh[i][2], xh[i][3], s0 + ad);
                ldsm4(xl[i][0], xl[i][1], xl[i][2], xl[i][3], s0 + 5120 + ad);
            }
            #pragma unroll
            for (int cg = 0; cg < 4; cg++) {
                int krow = ks * 16 + (sel & 1) * 8 + rr;
                int colb = (c0l + cg * 16) * 2 + (sel >> 1) * 16;
                uint32_t ad = s0 + bh_off + krow * 256 + (colb ^ ((krow & 7) << 4));
                uint32_t bh2[2][2], bl2[2][2];
                ldsm4t(bh2[0][0], bh2[0][1], bh2[1][0], bh2[1][1], ad);
                ldsm4t(bl2[0][0], bl2[0][1], bl2[1][0], bl2[1][1], ad + 8192);
                #pragma unroll
                for (int i = 0; i < 2; i++)
                    #pragma unroll
                    for (int h = 0; h < 2; h++) {
                        int cj = cg * 2 + h;
                        mma_bf16(acc[i][cj], xh[i], bh2[h]);
                        mma_bf16(acc[i][cj], xh[i], bl2[h]);
                        mma_bf16(acc[i][cj], xl[i], bh2[h]);
                    }
            }
        }
        __syncthreads();
    }
    CPA_WAIT0();

    int rq = lane >> 2, cq = (lane & 3) * 2;
    bool isYp = (cw >= 2);
    #pragma unroll
    for (int i = 0; i < 2; i++)
        #pragma unroll
        for (int cj = 0; cj < 8; cj++) {
            int c = c0l + cj * 8 + cq;
            size_t nr0 = (size_t)n0 + n0w + i * 16 + rq;
            size_t nr1 = nr0 + 8;
            float v0x = acc[i][cj].x, v0y = acc[i][cj].y;
            float v1x = acc[i][cj].z, v1y = acc[i][cj].w;
            if (isYp) {
                float d0 = g_d[nr0], d1 = g_d[nr1];
                v0x *= d0; v0y *= d0; v1x *= d1; v1y *= d1;
                *reinterpret_cast<float2*>(&g_Yp[nr0 * 128 + c]) = make_float2(v0x, v0y);
                *reinterpret_cast<float2*>(&g_Yp[nr1 * 128 + c]) = make_float2(v1x, v1y);
                *reinterpret_cast<__nv_bfloat162*>(&g_Yphi[nr0 * 128 + c]) =
                    __floats2bfloat162_rn(v0x, v0y);
                *reinterpret_cast<__nv_bfloat162*>(&g_Yphi[nr1 * 128 + c]) =
                    __floats2bfloat162_rn(v1x, v1y);
            } else {
                store_hilo2(g_Xehi, g_Xelo, nr0 * 128 + c, v0x, v0y);
                store_hilo2(g_Xehi, g_Xelo, nr1 * 128 + c, v1x, v1y);
            }
        }
}

// =====================================================================
// P1: 64x128 tile of A@Yphi, fused softmax (proven R14 config).
// grid (32,8), 256 thr, K-chunk 64, 2-stage, (256,2).
// =====================================================================
__global__ void __launch_bounds__(256, 2)
p1_logits(float* __restrict__ out) {
    extern __shared__ char smem[];
    uint32_t sb = smem_u32(smem);
    int tid = threadIdx.x;
    int wid = tid >> 5, lane = tid & 31;
    int n0 = blockIdx.x * 64, b = blockIdx.y;
    const __nv_bfloat16* Ag = g_Abf + ((size_t)b * 2048 + n0) * 2048;
    const __nv_bfloat16* Bg = g_Yphi + (size_t)b * 2048 * 128;

    float4 acc[2][4];
    #pragma unroll
    for (int i = 0; i < 2; i++)
        #pragma unroll
        for (int j = 0; j < 4; j++) acc[i][j] = make_float4(0.f, 0.f, 0.f, 0.f);

    int n0w = (wid >> 2) * 32, c0w = (wid & 3) * 32;
    int sel = lane >> 3, rr = lane & 7;

    auto stage = [&](int ch, int buf) {
        uint32_t s0 = sb + buf * P1BUF;
        int kc = ch * 64;
        #pragma unroll
        for (int q = 0; q < 2; q++) {
            int idx = tid + q * 256;
            int row = idx >> 3, u = idx & 7;
            cpa16(s0 + row * 144 + u * 16, Ag + (size_t)row * 2048 + kc + u * 8);
        }
        #pragma unroll
        for (int q = 0; q < 4; q++) {
            int idx = tid + q * 256;
            int k = idx >> 4, u = idx & 15;
            uint32_t so = k * 256 + ((u * 16) ^ ((k & 7) << 4));
            cpa16(s0 + 9216 + so, Bg + (size_t)(kc + k) * 128 + u * 8);
        }
        CPA_COMMIT();
    };

    stage(0, 0);
    for (int ch = 0; ch < 32; ch++) {
        if (ch < 31) { stage(ch + 1, (ch + 1) & 1); CPA_WAIT1(); }
        else CPA_WAIT0();
        __syncthreads();
        uint32_t s0 = sb + (ch & 1) * P1BUF;
        #pragma unroll
        for (int ks = 0; ks < 4; ks++) {
            uint32_t a[2][4];
            #pragma unroll
            for (int i = 0; i < 2; i++) {
                int row = n0w + i * 16 + (sel & 1) * 8 + rr;
                ldsm4(a[i][0], a[i][1], a[i][2], a[i][3],
                      s0 + row * 144 + ks * 32 + (sel >> 1) * 16);
            }
            uint32_t bh[4][2];
            #pragma unroll
            for (int cg = 0; cg < 2; cg++) {
                int krow = ks * 16 + (sel & 1) * 8 + rr;
                int colb = (c0w + cg * 16) * 2 + (sel >> 1) * 16;
                uint32_t ad = s0 + 9216 + krow * 256 + (colb ^ ((krow & 7) << 4));
                ldsm4t(bh[cg*2][0], bh[cg*2][1], bh[cg*2+1][0], bh[cg*2+1][1], ad);
            }
            #pragma unroll
            for (int i = 0; i < 2; i++)
                #pragma unroll
                for (int cj = 0; cj < 4; cj++)
                    mma_bf16(acc[i][cj], a[i], bh[cj]);
        }
        __syncthreads();
    }
    CPA_WAIT0();
    __syncthreads();

    float* smlog = reinterpret_cast<float*>(smem);    // [64][132] = 33792B
    int rq = lane >> 2, cq = (lane & 3) * 2;
    #pragma unroll
    for (int i = 0; i < 2; i++)
        #pragma unroll
        for (int cj = 0; cj < 4; cj++) {
            int rowl = n0w + i * 16 + rq;
            int col = c0w + cj * 8 + cq;
            *reinterpret_cast<float2*>(&smlog[rowl * 132 + col])       = make_float2(acc[i][cj].x, acc[i][cj].y);
            *reinterpret_cast<float2*>(&smlog[(rowl + 8) * 132 + col]) = make_float2(acc[i][cj].z, acc[i][cj].w);
        }
    __syncthreads();

    #pragma unroll
    for (int r = 0; r < 8; r++) {
        int rowl = wid * 8 + r;
        size_t nr = (size_t)b * 2048 + n0 + rowl;
        float dn = g_d[nr];
        float4 Lc = *reinterpret_cast<float4*>(&smlog[rowl * 132 + lane * 4]);
        float4 Yv = reinterpret_cast<const float4*>(g_Yp + nr * 128)[lane];
        float l0 = dn * (Lc.x + Yv.x), l1 = dn * (Lc.y + Yv.y);
        float l2 = dn * (Lc.z + Yv.z), l3 = dn * (Lc.w + Yv.w);
        float m = fmaxf(fmaxf(l0, l1), fmaxf(l2, l3));
        #pragma unroll
        for (int o = 16; o > 0; o >>= 1) m = fmaxf(m, __shfl_xor_sync(0xffffffffu, m, o));
        float e0 = expf(l0 - m), e1 = expf(l1 - m), e2 = expf(l2 - m), e3 = expf(l3 - m);
        float ss = (e0 + e1) + (e2 + e3);
        #pragma unroll
        for (int o = 16; o > 0; o >>= 1) ss += __shfl_xor_sync(0xffffffffu, ss, o);
        float inv = 1.f / ss;
        float s0v = e0 * inv, s1v = e1 * inv, s2v = e2 * inv, s3v = e3 * inv;
        reinterpret_cast<float4*>(out + OUT_S + nr * 128)[lane] = make_float4(s0v, s1v, s2v, s3v);
        store_hilo2(g_Shi, g_Slo, nr * 128 + lane * 4,     s0v, s1v);
        store_hilo2(g_Shi, g_Slo, nr * 128 + lane * 4 + 2, s2v, s3v);
        __nv_bfloat162 dh0 = __floats2bfloat162_rn(dn * s0v, dn * s1v);
        __nv_bfloat162 dh1 = __floats2bfloat162_rn(dn * s2v, dn * s3v);
        *reinterpret_cast<__nv_bfloat162*>(g_dShi + nr * 128 + lane * 4)     = dh0;
        *reinterpret_cast<__nv_bfloat162*>(g_dShi + nr * 128 + lane * 4 + 2) = dh1;
        float ent = -(s0v * logf(s0v + 1e-7f) + s1v * logf(s1v + 1e-7f)
                    + s2v * logf(s2v + 1e-7f) + s3v * logf(s3v + 1e-7f));
        #pragma unroll
        for (int o = 16; o > 0; o >>= 1) ent += __shfl_xor_sync(0xffffffffu, ent, o);
        if (lane == 0) g_entrRow[nr] = ent;
    }
}

// =====================================================================
// P2: 64x256 tile of A@[Shi | dShi] -> Thi/Tlo, Uhi/Ulo.
// grid (32,8), 256 thr, K-chunk 64, 2-stage, (256,2).
// =====================================================================
__global__ void __launch_bounds__(256, 2)
p2_TU(const float* __restrict__ out) {
    extern __shared__ char smem[];
    uint32_t sb = smem_u32(smem);
    int tid = threadIdx.x;
    int wid = tid >> 5, lane = tid & 31;
    int n0 = blockIdx.x * 64, b = blockIdx.y;
    const __nv_bfloat16* Ag = g_Abf + ((size_t)b * 2048 + n0) * 2048;
    const __nv_bfloat16* Sg = g_Shi + (size_t)b * 2048 * 128;
    const __nv_bfloat16* Dg = g_dShi + (size_t)b * 2048 * 128;

    float4 acc[2][8];
    #pragma unroll
    for (int i = 0; i < 2; i++)
        #pragma unroll
        for (int j = 0; j < 8; j++) acc[i][j] = make_float4(0.f, 0.f, 0.f, 0.f);

    int n0w = (wid >> 2) * 32;
    int cw = wid & 3;
    int c0l = (cw & 1) * 64;
    uint32_t bbase_off = 9216 + (cw >= 2 ? 16384u : 0u);
    int sel = lane >> 3, rr = lane & 7;

    auto stage = [&](int ch, int buf) {
        uint32_t s0 = sb + buf * P2BUF;
        int kc = ch * 64;
        #pragma unroll
        for (int q = 0; q < 2; q++) {
            int idx = tid + q * 256;
            int row = idx >> 3, u = idx & 7;
            cpa16(s0 + row * 144 + u * 16, Ag + (size_t)row * 2048 + kc + u * 8);
        }
        #pragma unroll
        for (int q = 0; q < 8; q++) {
            int idx = tid + q * 256;
            int blk = idx >> 10, r = idx & 1023;
            int k = r >> 4, u = r & 15;
            uint32_t so = k * 256 + ((u * 16) ^ ((k & 7) << 4));
            const __nv_bfloat16* src = blk ? Dg : Sg;
            cpa16(s0 + 9216 + blk * 16384 + so, src + (size_t)(kc + k) * 128 + u * 8);
        }
        CPA_COMMIT();
    };

    stage(0, 0);
    for (int ch = 0; ch < 32; ch++) {
        if (ch < 31) { stage(ch + 1, (ch + 1) & 1); CPA_WAIT1(); }
        else CPA_WAIT0();
        __syncthreads();
        uint32_t s0 = sb + (ch & 1) * P2BUF;
        #pragma unroll
        for (int ks = 0; ks < 4; ks++) {
            uint32_t a[2][4];
            #pragma unroll
            for (int i = 0; i < 2; i++) {
                int row = n0w + i * 16 + (sel & 1) * 8 + rr;
                ldsm4(a[i][0], a[i][1], a[i][2], a[i][3],
                      s0 + row * 144 + ks * 32 + (sel >> 1) * 16);
            }
            uint32_t bh[8][2];
            #pragma unroll
            for (int cg = 0; cg < 4; cg++) {
                int krow = ks * 16 + (sel & 1) * 8 + rr;
                int colb = (c0l + cg * 16) * 2 + (sel >> 1) * 16;
                uint32_t ad = s0 + bbase_off + krow * 256 + (colb ^ ((krow & 7) << 4));
                ldsm4t(bh[cg*2][0], bh[cg*2][1], bh[cg*2+1][0], bh[cg*2+1][1], ad);
            }
            #pragma unroll
            for (int i = 0; i < 2; i++)
                #pragma unroll
                for (int cj = 0; cj < 8; cj++)
                    mma_bf16(acc[i][cj], a[i], bh[cj]);
        }
        __syncthreads();
    }
    CPA_WAIT0();

    int rq = lane >> 2, cq = (lane & 3) * 2;
    bool isU = (cw >= 2);
    __nv_bfloat16* Hd = isU ? g_Uhi : g_Thi;
    __nv_bfloat16* Ld = isU ? g_Ulo : g_Tlo;
    #pragma unroll
    for (int i = 0; i < 2; i++)
        #pragma unroll
        for (int cj = 0; cj < 8; cj++) {
            int n = n0 + n0w + i * 16 + rq;
            int c = c0l + cj * 8 + cq;
            size_t nr0 = (size_t)b * 2048 + n;
            size_t nr1 = nr0 + 8;
            float v0x = acc[i][cj].x, v0y = acc[i][cj].y;
            float v1x = acc[i][cj].z, v1y = acc[i][cj].w;
            if (isU) {
                float d0 = g_d[nr0], d1 = g_d[nr1];
                float2 sv0 = *reinterpret_cast<const float2*>(&out[OUT_S + nr0 * 128 + c]);
                float2 sv1 = *reinterpret_cast<const float2*>(&out[OUT_S + nr1 * 128 + c]);
                v0x = d0 * v0x + d0 * d0 * sv0.x;
                v0y = d0 * v0y + d0 * d0 * sv0.y;
                v1x = d1 * v1x + d1 * d1 * sv1.x;
                v1y = d1 * v1y + d1 * d1 * sv1.y;
            }
            store_hilo2(Hd, Ld, nr0 * 128 + c, v0x, v0y);
            store_hilo2(Hd, Ld, nr1 * 128 + c, v1x, v1y);
        }
}

// =====================================================================
// K5T: tensorized L^T R, hi/lo (hh+hl+lh). Split-K over n; 3 bufs,
// 2 in flight, drain-aware tail. grid (8,8,3), 256 thr.
// =====================================================================
__global__ void __launch_bounds__(256, 2)
k5t_outer() {
    extern __shared__ char smem[];
    uint32_t sb = smem_u32(smem);
    int tid = threadIdx.x;
    int wid = tid >> 5, lane = tid & 31;
    int split = blockIdx.x, b = blockIdx.y, p = blockIdx.z;
    size_t boff = (size_t)b * 2048 * 128;

    const __nv_bfloat16* src[4];
    if (p == 0)      { src[0] = g_Uhi; src[1] = g_Ulo; src[2] = g_Xehi; src[3] = g_Xelo; }
    else if (p == 1) { src[0] = g_Shi; src[1] = g_Slo; src[2] = g_Thi;  src[3] = g_Tlo; }
    else             { src[0] = g_Shi; src[1] = g_Slo; src[2] = g_Shi;  src[3] = g_Slo; }

    float4 acc[2][8];
    #pragma unroll
    for (int i = 0; i < 2; i++)
        #pragma unroll
        for (int j = 0; j < 8; j++) acc[i][j] = make_float4(0.f, 0.f, 0.f, 0.f);

    int c1w = (wid >> 1) * 32, c2w = (wid & 1) * 64;
    int sel = lane >> 3, rr = lane & 7;

    auto stage = [&](int ch) {
        uint32_t s0 = sb + (ch % 3) * K5BUF;
        int nc = split * 256 + ch * 32;
        #pragma unroll
        for (int q = 0; q < 8; q++) {
            int arr = q >> 1;
            int r = ((q & 1) << 8) + tid;
            int k = r >> 4, u = r & 15;
            uint32_t so = k * 256 + ((u * 16) ^ ((k & 7) << 4));
            cpa16(s0 + arr * 8192 + so, src[arr] + boff + (size_t)(nc + k) * 128 + u * 8);
        }
        CPA_COMMIT();
    };

    stage(0); stage(1);
    for (int ch = 0; ch < 8; ch++) {
        if (ch < 7) CPA_WAIT1();
        else CPA_WAIT0();
        __syncthreads();
        uint32_t s0 = sb + (ch % 3) * K5BUF;
        #pragma unroll
        for (int ks = 0; ks < 2; ks++) {
            uint32_t lh[2][4], ll[2][4];
            #pragma unroll
            for (int i = 0; i < 2; i++) {
                int krow = ks * 16 + (sel >> 1) * 8 + rr;
                int colb = (c1w + i * 16 + (sel & 1) * 8) * 2;
                uint32_t ad = krow * 256 + (colb ^ ((krow & 7) << 4));
                ldsm4t(lh[i][0], lh[i][1], lh[i][2], lh[i][3], s0 + ad);
                ldsm4t(ll[i][0], ll[i][1], ll[i][2], ll[i][3], s0 + 8192 + ad);
            }
            #pragma unroll
            for (int cg = 0; cg < 4; cg++) {
                int krow = ks * 16 + (sel & 1) * 8 + rr;
                int colb = (c2w + cg * 16) * 2 + (sel >> 1) * 16;
                uint32_t ad = krow * 256 + (colb ^ ((krow & 7) << 4));
                uint32_t rh[2][2], rl[2][2];
                ldsm4t(rh[0][0], rh[0][1], rh[1][0], rh[1][1], s0 + 16384 + ad);
                ldsm4t(rl[0][0], rl[0][1], rl[1][0], rl[1][1], s0 + 24576 + ad);
                #pragma unroll
                for (int i = 0; i < 2; i++)
                    #pragma unroll
                    for (int h = 0; h < 2; h++) {
                        int cj = cg * 2 + h;
                        mma_bf16(acc[i][cj], lh[i], rh[h]);
                        mma_bf16(acc[i][cj], lh[i], rl[h]);
                        mma_bf16(acc[i][cj], ll[i], rh[h]);
                    }
            }
        }
        if (ch + 2 < 8) stage(ch + 2);
    }
    CPA_WAIT0();

    float* dst = g_part + ((size_t)((p * 8 + b) * 8 + split)) * 16384;
    int rq = lane >> 2, cq = (lane & 3) * 2;
    #pragma unroll
    for (int i = 0; i < 2; i++)
        #pragma unroll
        for (int cj = 0; cj < 8; cj++) {
            int c1 = c1w + i * 16 + rq;
            int c2 = c2w + cj * 8 + cq;
            *reinterpret_cast<float2*>(&dst[c1 * 128 + c2])       = make_float2(acc[i][cj].x, acc[i][cj].y);
            *reinterpret_cast<float2*>(&dst[(c1 + 8) * 128 + c2]) = make_float2(acc[i][cj].z, acc[i][cj].w);
        }
}

// =====================================================================
// K5b: reduce 8 split-K partials -> X_pooled, A_pooled (out), G
// =====================================================================
__global__ void k5b_reduce(float* __restrict__ out) {
    int idx = blockIdx.x * blockDim.x + threadIdx.x;
    if (idx >= 3 * 8 * 16384) return;
    int p = idx / 131072;
    int rem = idx - p * 131072;
    int b = rem >> 14;
    int kc = rem & 16383;
    const float* s0 = g_part + ((size_t)(p * 8 + b) * 8) * 16384 + kc;
    float s = 0.f;
    #pragma unroll
    for (int ch = 0; ch < 8; ch++) s += s0[(size_t)ch * 16384];
    if (p == 0)      out[(size_t)b * 16384 + kc] = s;
    else if (p == 1) out[OUT_AP + (size_t)b * 16384 + kc] = s;
    else             g_G[b * 16384 + kc] = s;
}

// =====================================================================
// K6: losses. LP_b^2 = sumA_b - 2 tr(A_pooled_b) + ||G_b||_F^2
// =====================================================================
__global__ void k6_final(float* __restrict__ out) {
    int t = threadIdx.x;
    __shared__ float red[256];

    float lo = 0.f;
    for (int i = t; i < ROWS; i += 256) lo += g_entrRow[i];
    red[t] = lo; __syncthreads();
    for (int s2 = 128; s2 > 0; s2 >>= 1) {
        if (t < s2) red[t] += red[t + s2];
        __syncthreads();
    }
    float entr = red[0] / (float)ROWS;
    __syncthreads();

    float lpsum = 0.f;
    for (int b = 0; b < 8; b++) {
        float la = 0.f;
        for (int i = t; i < NN; i += 256) la += (float)g_nnz[b * NN + i];
        red[t] = la; __syncthreads();
        for (int s2 = 128; s2 > 0; s2 >>= 1) { if (t < s2) red[t] += red[t + s2]; __syncthreads(); }
        float sumA = red[0]; __syncthreads();

        float ltr = (t < 128) ? out[OUT_AP + (size_t)b * 16384 + t * 129] : 0.f;
        red[t] = ltr; __syncthreads();
        for (int s2 = 128; s2 > 0; s2 >>= 1) { if (t < s2) red[t] += red[t + s2]; __syncthreads(); }
        float tr = red[0]; __syncthreads();

        float lg = 0.f;
        for (int i = t; i < 16384; i += 256) { float v = g_G[b * 16384 + i]; lg += v * v; }
        red[t] = lg; __syncthreads();
        for (int s2 = 128; s2 > 0; s2 >>= 1) { if (t < s2) red[t] += red[t + s2]; __syncthreads(); }
        float gg = red[0]; __syncthreads();

        lpsum += sqrtf(fmaxf(sumA - 2.f * tr + gg, 0.f));
    }
    if (t == 0) {
        out[OUT_LP] = lpsum / 8.0f;
        out[OUT_ENT] = entr;
    }
}

// =====================================================================
extern "C" void kernel_launch(void* const* d_in, const int* in_sizes, int n_in,
                              void* d_out, int out_size) {
    const float* X  = (const float*)d_in[0];
    const float* A  = (const float*)d_in[1];
    const float* We = (const float*)d_in[2];
    const float* Wp = (const float*)d_in[3];
    float* out = (float*)d_out;

    cudaFuncSetAttribute(k2t_xw, cudaFuncAttributeMaxDynamicSharedMemorySize, K2SMEM);
    cudaFuncSetAttribute(p1_logits, cudaFuncAttributeMaxDynamicSharedMemorySize, P1SMEM);
    cudaFuncSetAttribute(p2_TU, cudaFuncAttributeMaxDynamicSharedMemorySize, P2SMEM);
    cudaFuncSetAttribute(k5t_outer, cudaFuncAttributeMaxDynamicSharedMemorySize, K5SMEM);

    k1_scan<<<ROWS, 256>>>(A);
    k0_convX<<<1024, 256>>>(X);
    kW_conv<<<32, 256>>>(We, Wp);
    k2t_xw<<<256, 256, K2SMEM>>>();
    dim3 gd(32, 8);
    p1_logits<<<gd, 256, P1SMEM>>>(out);
    p2_TU<<<gd, 256, P2SMEM>>>(out);
    dim3 g5(8, 8, 3);
    k5t_outer<<<g5, 256, K5SMEM>>>();
    k5b_reduce<<<(3 * 8 * 16384 + 255) / 256, 256>>>(out);
    k6_final<<<1, 256>>>(out);
}